// round 1
// baseline (speedup 1.0000x reference)
#include <cuda_runtime.h>

#define N_TOK 8192
#define EMB 1024
#define HID 4096
#define NE 8

// ---------------- device scratch (no allocations allowed) ----------------
__device__ float g_H[(size_t)N_TOK * EMB];        // router hidden (relu(x@Wr1+br1))
__device__ float g_hidden[(size_t)N_TOK * HID];   // expert hidden, rows in permuted order
__device__ int   g_chosen[N_TOK];
__device__ int   g_counts[NE];
__device__ int   g_offsets[NE + 1];
__device__ int   g_cursor[NE];
__device__ int   g_perm[N_TOK];                   // perm[pos] = token id, contiguous per expert

// ---------------- router GEMM: g_H = relu(x @ Wr1 + br1) ----------------
// M=8192, N=1024, K=1024. BM=BN=128, BK=8, 256 threads, 8x8 per thread.
__global__ __launch_bounds__(256, 2)
void sgemm_router(const float* __restrict__ A, const float* __restrict__ B,
                  const float* __restrict__ bias)
{
    const int K = EMB, N = EMB;
    __shared__ float As[8][128];
    __shared__ float Bs[8][128];
    const int tid = threadIdx.x;
    const int m0 = blockIdx.x * 128;
    const int n0 = blockIdx.y * 128;
    const int arow = tid >> 1;
    const int acol = (tid & 1) * 4;
    const int brow = tid >> 5;
    const int bcol = (tid & 31) * 4;
    const float* Ap = A + (size_t)(m0 + arow) * K + acol;
    const float* Bp = B + (size_t)brow * N + n0 + bcol;
    const int ty = (tid >> 4) * 8;
    const int tx = (tid & 15) * 8;
    float acc[8][8];
#pragma unroll
    for (int i = 0; i < 8; i++)
#pragma unroll
        for (int j = 0; j < 8; j++) acc[i][j] = 0.f;

    for (int k0 = 0; k0 < K; k0 += 8) {
        float4 av = *(const float4*)(Ap + k0);
        float4 bv = *(const float4*)(Bp + (size_t)k0 * N);
        As[acol + 0][arow] = av.x;
        As[acol + 1][arow] = av.y;
        As[acol + 2][arow] = av.z;
        As[acol + 3][arow] = av.w;
        *(float4*)&Bs[brow][bcol] = bv;
        __syncthreads();
#pragma unroll
        for (int kk = 0; kk < 8; kk++) {
            float a[8], b[8];
            *(float4*)&a[0] = *(const float4*)&As[kk][ty];
            *(float4*)&a[4] = *(const float4*)&As[kk][ty + 4];
            *(float4*)&b[0] = *(const float4*)&Bs[kk][tx];
            *(float4*)&b[4] = *(const float4*)&Bs[kk][tx + 4];
#pragma unroll
            for (int i = 0; i < 8; i++)
#pragma unroll
                for (int j = 0; j < 8; j++) acc[i][j] = fmaf(a[i], b[j], acc[i][j]);
        }
        __syncthreads();
    }
#pragma unroll
    for (int i = 0; i < 8; i++) {
        float* Cp = g_H + (size_t)(m0 + ty + i) * N + n0 + tx;
#pragma unroll
        for (int j = 0; j < 8; j += 4) {
            float4 v;
            v.x = fmaxf(acc[i][j + 0] + bias[n0 + tx + j + 0], 0.f);
            v.y = fmaxf(acc[i][j + 1] + bias[n0 + tx + j + 1], 0.f);
            v.z = fmaxf(acc[i][j + 2] + bias[n0 + tx + j + 2], 0.f);
            v.w = fmaxf(acc[i][j + 3] + bias[n0 + tx + j + 3], 0.f);
            *(float4*)(Cp + j) = v;
        }
    }
}

// ---------------- router logits + argmax + histogram ----------------
__global__ void init_counts()
{
    if (threadIdx.x < NE) g_counts[threadIdx.x] = 0;
}

// one warp per token: logits[e] = g_H[t,:] @ Wr2[:,e] + br2[e]; argmax
__global__ __launch_bounds__(256)
void router_argmax(const float* __restrict__ Wr2, const float* __restrict__ br2)
{
    int gid = blockIdx.x * blockDim.x + threadIdx.x;
    int t = gid >> 5;
    int lane = gid & 31;
    if (t >= N_TOK) return;
    const float* h = g_H + (size_t)t * EMB;
    float acc[NE];
#pragma unroll
    for (int e = 0; e < NE; e++) acc[e] = 0.f;
    for (int i = lane; i < EMB; i += 32) {
        float hv = h[i];
        const float4 w0 = *(const float4*)(Wr2 + (size_t)i * NE);
        const float4 w1 = *(const float4*)(Wr2 + (size_t)i * NE + 4);
        acc[0] = fmaf(hv, w0.x, acc[0]);
        acc[1] = fmaf(hv, w0.y, acc[1]);
        acc[2] = fmaf(hv, w0.z, acc[2]);
        acc[3] = fmaf(hv, w0.w, acc[3]);
        acc[4] = fmaf(hv, w1.x, acc[4]);
        acc[5] = fmaf(hv, w1.y, acc[5]);
        acc[6] = fmaf(hv, w1.z, acc[6]);
        acc[7] = fmaf(hv, w1.w, acc[7]);
    }
#pragma unroll
    for (int off = 16; off > 0; off >>= 1)
#pragma unroll
        for (int e = 0; e < NE; e++)
            acc[e] += __shfl_xor_sync(0xffffffffu, acc[e], off);
    if (lane == 0) {
        int best = 0;
        float bv = acc[0] + br2[0];
#pragma unroll
        for (int e = 1; e < NE; e++) {
            float v = acc[e] + br2[e];
            if (v > bv) { bv = v; best = e; }  // strict > : first-max, matches jnp.argmax
        }
        g_chosen[t] = best;
        atomicAdd(&g_counts[best], 1);
    }
}

__global__ void scan_offsets()
{
    if (threadIdx.x == 0 && blockIdx.x == 0) {
        int o = 0;
        for (int e = 0; e < NE; e++) {
            g_offsets[e] = o;
            g_cursor[e] = o;
            o += g_counts[e];
        }
        g_offsets[NE] = o;
    }
}

__global__ void scatter_tokens()
{
    int t = blockIdx.x * blockDim.x + threadIdx.x;
    if (t >= N_TOK) return;
    int e = g_chosen[t];
    int pos = atomicAdd(&g_cursor[e], 1);
    g_perm[pos] = t;  // order within expert is arbitrary; output is token-indexed
}

// ---------------- expert FFN GEMM 1: hidden = relu(x[perm] @ W1[e] + b1[e]) ----------------
// K=1024, N=4096; rows are the expert's token segment [offsets[e], offsets[e+1]).
__global__ __launch_bounds__(256, 2)
void expert_ffn1(const float* __restrict__ X, const float* __restrict__ W1,
                 const float* __restrict__ b1)
{
    const int K = EMB, N = HID;
    const int e = blockIdx.z;
    const int start = g_offsets[e], end = g_offsets[e + 1];
    const int m0 = start + blockIdx.x * 128;
    if (m0 >= end) return;
    const float* B = W1 + (size_t)e * K * N;
    const float* bias = b1 + (size_t)e * N;

    __shared__ float As[8][128];
    __shared__ float Bs[8][128];
    const int tid = threadIdx.x;
    const int n0 = blockIdx.y * 128;
    const int arow = tid >> 1;
    const int acol = (tid & 1) * 4;
    const int brow = tid >> 5;
    const int bcol = (tid & 31) * 4;
    const int r = m0 + arow;
    const int tok = (r < end) ? g_perm[r] : 0;   // safe dummy row; result row never stored
    const float* Ap = X + (size_t)tok * K + acol;
    const float* Bp = B + (size_t)brow * N + n0 + bcol;
    const int ty = (tid >> 4) * 8;
    const int tx = (tid & 15) * 8;
    float acc[8][8];
#pragma unroll
    for (int i = 0; i < 8; i++)
#pragma unroll
        for (int j = 0; j < 8; j++) acc[i][j] = 0.f;

    for (int k0 = 0; k0 < K; k0 += 8) {
        float4 av = *(const float4*)(Ap + k0);
        float4 bv = *(const float4*)(Bp + (size_t)k0 * N);
        As[acol + 0][arow] = av.x;
        As[acol + 1][arow] = av.y;
        As[acol + 2][arow] = av.z;
        As[acol + 3][arow] = av.w;
        *(float4*)&Bs[brow][bcol] = bv;
        __syncthreads();
#pragma unroll
        for (int kk = 0; kk < 8; kk++) {
            float a[8], b[8];
            *(float4*)&a[0] = *(const float4*)&As[kk][ty];
            *(float4*)&a[4] = *(const float4*)&As[kk][ty + 4];
            *(float4*)&b[0] = *(const float4*)&Bs[kk][tx];
            *(float4*)&b[4] = *(const float4*)&Bs[kk][tx + 4];
#pragma unroll
            for (int i = 0; i < 8; i++)
#pragma unroll
                for (int j = 0; j < 8; j++) acc[i][j] = fmaf(a[i], b[j], acc[i][j]);
        }
        __syncthreads();
    }
#pragma unroll
    for (int i = 0; i < 8; i++) {
        int rr = m0 + ty + i;
        if (rr < end) {
            float* Cp = g_hidden + (size_t)rr * N + n0 + tx;
#pragma unroll
            for (int j = 0; j < 8; j += 4) {
                float4 v;
                v.x = fmaxf(acc[i][j + 0] + bias[n0 + tx + j + 0], 0.f);
                v.y = fmaxf(acc[i][j + 1] + bias[n0 + tx + j + 1], 0.f);
                v.z = fmaxf(acc[i][j + 2] + bias[n0 + tx + j + 2], 0.f);
                v.w = fmaxf(acc[i][j + 3] + bias[n0 + tx + j + 3], 0.f);
                *(float4*)(Cp + j) = v;
            }
        }
    }
}

// ---------------- expert FFN GEMM 2: out[perm] = hidden @ W2[e] + b2[e] ----------------
// K=4096, N=1024.
__global__ __launch_bounds__(256, 2)
void expert_ffn2(const float* __restrict__ W2, const float* __restrict__ b2,
                 float* __restrict__ out)
{
    const int K = HID, N = EMB;
    const int e = blockIdx.z;
    const int start = g_offsets[e], end = g_offsets[e + 1];
    const int m0 = start + blockIdx.x * 128;
    if (m0 >= end) return;
    const float* B = W2 + (size_t)e * K * N;
    const float* bias = b2 + (size_t)e * N;

    __shared__ float As[8][128];
    __shared__ float Bs[8][128];
    const int tid = threadIdx.x;
    const int n0 = blockIdx.y * 128;
    const int arow = tid >> 1;
    const int acol = (tid & 1) * 4;
    const int brow = tid >> 5;
    const int bcol = (tid & 31) * 4;
    const int r = m0 + arow;
    const int ra = (r < end) ? r : start;  // clamp to a valid row, value unused
    const float* Ap = g_hidden + (size_t)ra * K + acol;
    const float* Bp = B + (size_t)brow * N + n0 + bcol;
    const int ty = (tid >> 4) * 8;
    const int tx = (tid & 15) * 8;
    float acc[8][8];
#pragma unroll
    for (int i = 0; i < 8; i++)
#pragma unroll
        for (int j = 0; j < 8; j++) acc[i][j] = 0.f;

    for (int k0 = 0; k0 < K; k0 += 8) {
        float4 av = *(const float4*)(Ap + k0);
        float4 bv = *(const float4*)(Bp + (size_t)k0 * N);
        As[acol + 0][arow] = av.x;
        As[acol + 1][arow] = av.y;
        As[acol + 2][arow] = av.z;
        As[acol + 3][arow] = av.w;
        *(float4*)&Bs[brow][bcol] = bv;
        __syncthreads();
#pragma unroll
        for (int kk = 0; kk < 8; kk++) {
            float a[8], b[8];
            *(float4*)&a[0] = *(const float4*)&As[kk][ty];
            *(float4*)&a[4] = *(const float4*)&As[kk][ty + 4];
            *(float4*)&b[0] = *(const float4*)&Bs[kk][tx];
            *(float4*)&b[4] = *(const float4*)&Bs[kk][tx + 4];
#pragma unroll
            for (int i = 0; i < 8; i++)
#pragma unroll
                for (int j = 0; j < 8; j++) acc[i][j] = fmaf(a[i], b[j], acc[i][j]);
        }
        __syncthreads();
    }
#pragma unroll
    for (int i = 0; i < 8; i++) {
        int rr = m0 + ty + i;
        if (rr < end) {
            int tok = g_perm[rr];
            float* Cp = out + (size_t)tok * N + n0 + tx;
#pragma unroll
            for (int j = 0; j < 8; j += 4) {
                float4 v;
                v.x = acc[i][j + 0] + bias[n0 + tx + j + 0];
                v.y = acc[i][j + 1] + bias[n0 + tx + j + 1];
                v.z = acc[i][j + 2] + bias[n0 + tx + j + 2];
                v.w = acc[i][j + 3] + bias[n0 + tx + j + 3];
                *(float4*)(Cp + j) = v;
            }
        }
    }
}

// ---------------- launch ----------------
extern "C" void kernel_launch(void* const* d_in, const int* in_sizes, int n_in,
                              void* d_out, int out_size)
{
    const float* x   = (const float*)d_in[0];
    const float* Wr1 = (const float*)d_in[1];
    const float* br1 = (const float*)d_in[2];
    const float* Wr2 = (const float*)d_in[3];
    const float* br2 = (const float*)d_in[4];
    const float* W1  = (const float*)d_in[5];
    const float* b1  = (const float*)d_in[6];
    const float* W2  = (const float*)d_in[7];
    const float* b2  = (const float*)d_in[8];
    float* out = (float*)d_out;

    init_counts<<<1, 32>>>();
    sgemm_router<<<dim3(N_TOK / 128, EMB / 128), 256>>>(x, Wr1, br1);
    router_argmax<<<(N_TOK * 32) / 256, 256>>>(Wr2, br2);
    scan_offsets<<<1, 1>>>();
    scatter_tokens<<<N_TOK / 256, 256>>>();
    // every token belongs to exactly one expert, so out is fully written
    expert_ffn1<<<dim3(N_TOK / 128, HID / 128, NE), 256>>>(x, W1, b1);
    expert_ffn2<<<dim3(N_TOK / 128, EMB / 128, NE), 256>>>(W2, b2, out);
}